// round 15
// baseline (speedup 1.0000x reference)
#include <cuda_runtime.h>
#include <cuda_fp16.h>

#define N_NODES 50000
#define N_EDGES 800000
#define CAP     64            // bucket capacity; max degree ~42 (Poisson 16)

// -------- scratch (static device allocations; no cudaMalloc allowed) --------
__device__ __half g_h1h[N_NODES * 64];     // GEMM out (half) -> agg gather input
__device__ __half g_h2h[N_NODES * 64];     // agg1 out (half) -> gemm2 input
__device__ float  g_h2f[N_NODES * 64];     // agg2 out (fp32) -> head input
__device__ int    g_cnt[N_NODES];          // zero at entry; agg2 re-zeroes
__device__ int2   g_edge[N_NODES * CAP];   // bucketed (src, weight-bits)

// ---------------------------- PTX helpers -----------------------------------
__device__ __forceinline__ unsigned smem_u32(const void* p) {
    return (unsigned)__cvta_generic_to_shared(p);
}
__device__ __forceinline__ void ldsm_x4(unsigned& r0, unsigned& r1,
                                        unsigned& r2, unsigned& r3, unsigned a) {
    asm volatile("ldmatrix.sync.aligned.m8n8.x4.shared.b16 {%0,%1,%2,%3},[%4];\n"
                 : "=r"(r0), "=r"(r1), "=r"(r2), "=r"(r3) : "r"(a));
}
__device__ __forceinline__ void ldsm_x4_t(unsigned& r0, unsigned& r1,
                                          unsigned& r2, unsigned& r3, unsigned a) {
    asm volatile("ldmatrix.sync.aligned.m8n8.x4.trans.shared.b16 {%0,%1,%2,%3},[%4];\n"
                 : "=r"(r0), "=r"(r1), "=r"(r2), "=r"(r3) : "r"(a));
}
__device__ __forceinline__ void mma16816(float* d, unsigned a0, unsigned a1,
                                         unsigned a2, unsigned a3,
                                         unsigned b0, unsigned b1) {
    asm volatile("mma.sync.aligned.m16n8k16.row.col.f32.f16.f16.f32 "
                 "{%0,%1,%2,%3},{%4,%5,%6,%7},{%8,%9},{%0,%1,%2,%3};\n"
                 : "+f"(d[0]), "+f"(d[1]), "+f"(d[2]), "+f"(d[3])
                 : "r"(a0), "r"(a1), "r"(a2), "r"(a3), "r"(b0), "r"(b1));
}

// ------------------- single-pass bucketed edge fill -------------------------
__global__ void fill_kernel(const int* __restrict__ src,
                            const int* __restrict__ dst,
                            const float* __restrict__ w) {
    const int stride = gridDim.x * blockDim.x;
    int i = blockIdx.x * blockDim.x + threadIdx.x;
#pragma unroll
    for (int j = 0; j < 4; j++, i += stride) {
        if (i < N_EDGES) {
            int d = dst[i];
            int r = atomicAdd(&g_cnt[d], 1);
            if (r < CAP)
                g_edge[d * CAP + r] = make_int2(src[i], __float_as_int(w[i]));
        }
    }
}

// ------------------- HMMA GEMM: 64 rows x 64 cols per block -----------------
// fp32-input variant (layer 1: A = x)
__global__ void gemm64_hmma_f32(const float* __restrict__ A,
                                const float* __restrict__ W,
                                __half* __restrict__ outh) {
    __shared__ __align__(16) __half As[64 * 72];
    __shared__ __align__(16) __half Ws[64 * 72];
    const int tid  = threadIdx.x;
    const int lane = tid & 31;
    const int w    = tid >> 5;
    const int row0 = blockIdx.x * 64;

    const float4* W4 = reinterpret_cast<const float4*>(W);
    for (int i = tid; i < 1024; i += 128) {
        float4 v = W4[i];
        int k = i >> 4, n = (i & 15) * 4;
        __half2* p = reinterpret_cast<__half2*>(&Ws[k * 72 + n]);
        p[0] = __floats2half2_rn(v.x, v.y);
        p[1] = __floats2half2_rn(v.z, v.w);
    }
    const float4* A4 = reinterpret_cast<const float4*>(A);
    for (int i = tid; i < 1024; i += 128) {
        int r = i >> 4, k = (i & 15) * 4;
        int grow = row0 + r;
        float4 v = (grow < N_NODES) ? A4[grow * 16 + (k >> 2)]
                                    : make_float4(0.f, 0.f, 0.f, 0.f);
        __half2* p = reinterpret_cast<__half2*>(&As[r * 72 + k]);
        p[0] = __floats2half2_rn(v.x, v.y);
        p[1] = __floats2half2_rn(v.z, v.w);
    }
    __syncthreads();

    float d[4][2][4];
#pragma unroll
    for (int m = 0; m < 4; m++)
#pragma unroll
        for (int j = 0; j < 2; j++)
#pragma unroll
            for (int c = 0; c < 4; c++) d[m][j][c] = 0.f;

    const int lrow = lane & 15;
    const int lcol = (lane >> 4) * 8;

#pragma unroll
    for (int ks = 0; ks < 4; ks++) {
        const int kk = ks * 16;
        unsigned b0, b1, b2, b3;
        ldsm_x4_t(b0, b1, b2, b3,
                  smem_u32(&Ws[(kk + lrow) * 72 + w * 16 + lcol]));
#pragma unroll
        for (int m = 0; m < 4; m++) {
            unsigned a0, a1, a2, a3;
            ldsm_x4(a0, a1, a2, a3,
                    smem_u32(&As[(m * 16 + lrow) * 72 + kk + lcol]));
            mma16816(d[m][0], a0, a1, a2, a3, b0, b1);
            mma16816(d[m][1], a0, a1, a2, a3, b2, b3);
        }
    }

    __half2* out2 = reinterpret_cast<__half2*>(outh);
    const int r_in = lane >> 2;
    const int cpair = (lane & 3);
#pragma unroll
    for (int m = 0; m < 4; m++) {
#pragma unroll
        for (int j = 0; j < 2; j++) {
            int col2 = (w * 16 + j * 8) / 2 + cpair;
            int g0 = row0 + m * 16 + r_in;
            int g1 = g0 + 8;
            if (g0 < N_NODES)
                out2[g0 * 32 + col2] = __floats2half2_rn(d[m][j][0], d[m][j][1]);
            if (g1 < N_NODES)
                out2[g1 * 32 + col2] = __floats2half2_rn(d[m][j][2], d[m][j][3]);
        }
    }
}

// half-input variant (layer 2: A = agg1 half output)
__global__ void gemm64_hmma_f16(const __half* __restrict__ A,
                                const float* __restrict__ W,
                                __half* __restrict__ outh) {
    __shared__ __align__(16) __half As[64 * 72];
    __shared__ __align__(16) __half Ws[64 * 72];
    const int tid  = threadIdx.x;
    const int lane = tid & 31;
    const int w    = tid >> 5;
    const int row0 = blockIdx.x * 64;

    const float4* W4 = reinterpret_cast<const float4*>(W);
    for (int i = tid; i < 1024; i += 128) {
        float4 v = W4[i];
        int k = i >> 4, n = (i & 15) * 4;
        __half2* p = reinterpret_cast<__half2*>(&Ws[k * 72 + n]);
        p[0] = __floats2half2_rn(v.x, v.y);
        p[1] = __floats2half2_rn(v.z, v.w);
    }
    const uint2* A2 = reinterpret_cast<const uint2*>(A);
    for (int i = tid; i < 1024; i += 128) {
        int r = i >> 4, k4 = (i & 15);
        int grow = row0 + r;
        uint2 v = (grow < N_NODES) ? A2[grow * 16 + k4] : make_uint2(0u, 0u);
        *reinterpret_cast<uint2*>(&As[r * 72 + k4 * 4]) = v;
    }
    __syncthreads();

    float d[4][2][4];
#pragma unroll
    for (int m = 0; m < 4; m++)
#pragma unroll
        for (int j = 0; j < 2; j++)
#pragma unroll
            for (int c = 0; c < 4; c++) d[m][j][c] = 0.f;

    const int lrow = lane & 15;
    const int lcol = (lane >> 4) * 8;

#pragma unroll
    for (int ks = 0; ks < 4; ks++) {
        const int kk = ks * 16;
        unsigned b0, b1, b2, b3;
        ldsm_x4_t(b0, b1, b2, b3,
                  smem_u32(&Ws[(kk + lrow) * 72 + w * 16 + lcol]));
#pragma unroll
        for (int m = 0; m < 4; m++) {
            unsigned a0, a1, a2, a3;
            ldsm_x4(a0, a1, a2, a3,
                    smem_u32(&As[(m * 16 + lrow) * 72 + kk + lcol]));
            mma16816(d[m][0], a0, a1, a2, a3, b0, b1);
            mma16816(d[m][1], a0, a1, a2, a3, b2, b3);
        }
    }

    __half2* out2 = reinterpret_cast<__half2*>(outh);
    const int r_in = lane >> 2;
    const int cpair = (lane & 3);
#pragma unroll
    for (int m = 0; m < 4; m++) {
#pragma unroll
        for (int j = 0; j < 2; j++) {
            int col2 = (w * 16 + j * 8) / 2 + cpair;
            int g0 = row0 + m * 16 + r_in;
            int g1 = g0 + 8;
            if (g0 < N_NODES)
                out2[g0 * 32 + col2] = __floats2half2_rn(d[m][j][0], d[m][j][1]);
            if (g1 < N_NODES)
                out2[g1 * 32 + col2] = __floats2half2_rn(d[m][j][2], d[m][j][3]);
        }
    }
}

// -------------------- bucketed aggregation + bias + swish -------------------
// one warp per node; lane owns half2; 8x unroll (R8 form — best known).
// ZERO_CNT (agg2): lane 0 re-zeroes g_cnt[node] after reading the degree,
// restoring the zero-at-entry invariant for the next replay.
template<bool HALF_OUT, bool ZERO_CNT>
__global__ void agg_swish_kernel(const __half2* __restrict__ hp,
                                 const float* __restrict__ bias,
                                 void* __restrict__ outv) {
    int node = (blockIdx.x * blockDim.x + threadIdx.x) >> 5;
    int lane = threadIdx.x & 31;
    if (node >= N_NODES) return;
    int deg = g_cnt[node];
    if (deg > CAP) deg = CAP;
    if (ZERO_CNT && lane == 0) g_cnt[node] = 0;
    int beg = node * CAP;
    int end = beg + deg;
    float2 acc = make_float2(0.f, 0.f);
    int e = beg;
    for (; e + 8 <= end; e += 8) {
        int2 ed[8];
#pragma unroll
        for (int j = 0; j < 8; j++) ed[j] = g_edge[e + j];
        float2 v[8];
#pragma unroll
        for (int j = 0; j < 8; j++) v[j] = __half22float2(hp[ed[j].x * 32 + lane]);
#pragma unroll
        for (int j = 0; j < 8; j++) {
            float w = __int_as_float(ed[j].y);
            acc.x = fmaf(w, v[j].x, acc.x);
            acc.y = fmaf(w, v[j].y, acc.y);
        }
    }
    for (; e + 2 <= end; e += 2) {
        int2 e0 = g_edge[e], e1 = g_edge[e + 1];
        float2 v0 = __half22float2(hp[e0.x * 32 + lane]);
        float2 v1 = __half22float2(hp[e1.x * 32 + lane]);
        float w0 = __int_as_float(e0.y), w1 = __int_as_float(e1.y);
        acc.x = fmaf(w0, v0.x, acc.x); acc.y = fmaf(w0, v0.y, acc.y);
        acc.x = fmaf(w1, v1.x, acc.x); acc.y = fmaf(w1, v1.y, acc.y);
    }
    if (e < end) {
        int2 e0 = g_edge[e];
        float2 v0 = __half22float2(hp[e0.x * 32 + lane]);
        float w0 = __int_as_float(e0.y);
        acc.x = fmaf(w0, v0.x, acc.x); acc.y = fmaf(w0, v0.y, acc.y);
    }
    float2 b = reinterpret_cast<const float2*>(bias)[lane];
    float ax = acc.x + b.x;
    float ay = acc.y + b.y;
    ax = ax / (1.f + __expf(-ax));
    ay = ay / (1.f + __expf(-ay));
    if (HALF_OUT) {
        reinterpret_cast<__half2*>(outv)[node * 32 + lane] = __floats2half2_rn(ax, ay);
    } else {
        reinterpret_cast<float2*>(outv)[node * 32 + lane] = make_float2(ax, ay);
    }
}

// -------- HMMA fused head: dense(100, swish) + dense(1, sigmoid) ------------
__global__ void head_hmma_kernel(const float* __restrict__ A,
                                 const float* __restrict__ Wd,
                                 const float* __restrict__ bd,
                                 const float* __restrict__ Wo,
                                 const float* __restrict__ bo,
                                 float* __restrict__ out) {
    __shared__ __align__(16) __half As[64 * 72];
    __shared__ __align__(16) __half Ws[64 * 120];   // [k][n], n padded to 112
    __shared__ float bdS[112];
    __shared__ float woS[112];
    const int tid  = threadIdx.x;
    const int lane = tid & 31;
    const int w    = tid >> 5;
    const int row0 = blockIdx.x * 64;

    for (int i = tid; i < 64 * 112; i += 128) {
        int k = i / 112, n = i % 112;
        float v = (n < 100) ? Wd[k * 100 + n] : 0.f;
        Ws[k * 120 + n] = __float2half_rn(v);
    }
    const float4* A4 = reinterpret_cast<const float4*>(A);
    for (int i = tid; i < 1024; i += 128) {
        int r = i >> 4, k = (i & 15) * 4;
        int grow = row0 + r;
        float4 v = (grow < N_NODES) ? A4[grow * 16 + (k >> 2)]
                                    : make_float4(0.f, 0.f, 0.f, 0.f);
        __half2* p = reinterpret_cast<__half2*>(&As[r * 72 + k]);
        p[0] = __floats2half2_rn(v.x, v.y);
        p[1] = __floats2half2_rn(v.z, v.w);
    }
    if (tid < 112) {
        bdS[tid] = (tid < 100) ? bd[tid] : 0.f;
        woS[tid] = (tid < 100) ? Wo[tid] : 0.f;
    }
    __syncthreads();

    float acc[14][4];
#pragma unroll
    for (int t = 0; t < 14; t++)
#pragma unroll
        for (int c = 0; c < 4; c++) acc[t][c] = 0.f;

    const int lrow = lane & 15;
    const int lcol = (lane >> 4) * 8;

#pragma unroll
    for (int ks = 0; ks < 4; ks++) {
        const int kk = ks * 16;
        unsigned a0, a1, a2, a3;
        ldsm_x4(a0, a1, a2, a3,
                smem_u32(&As[(w * 16 + lrow) * 72 + kk + lcol]));
#pragma unroll
        for (int t2 = 0; t2 < 7; t2++) {
            unsigned b0, b1, b2, b3;
            ldsm_x4_t(b0, b1, b2, b3,
                      smem_u32(&Ws[(kk + lrow) * 120 + t2 * 16 + lcol]));
            mma16816(acc[t2 * 2],     a0, a1, a2, a3, b0, b1);
            mma16816(acc[t2 * 2 + 1], a0, a1, a2, a3, b2, b3);
        }
    }

    const int r_in = lane >> 2;
    const int c2   = (lane & 3) * 2;
    float s0 = 0.f, s1 = 0.f;
#pragma unroll
    for (int t = 0; t < 14; t++) {
        int c = t * 8 + c2;
        float bb0 = bdS[c], bb1 = bdS[c + 1];
        float ww0 = woS[c], ww1 = woS[c + 1];
        float v;
        v = acc[t][0] + bb0; v = v / (1.f + __expf(-v)); s0 = fmaf(v, ww0, s0);
        v = acc[t][1] + bb1; v = v / (1.f + __expf(-v)); s0 = fmaf(v, ww1, s0);
        v = acc[t][2] + bb0; v = v / (1.f + __expf(-v)); s1 = fmaf(v, ww0, s1);
        v = acc[t][3] + bb1; v = v / (1.f + __expf(-v)); s1 = fmaf(v, ww1, s1);
    }
    s0 += __shfl_xor_sync(0xffffffffu, s0, 1);
    s0 += __shfl_xor_sync(0xffffffffu, s0, 2);
    s1 += __shfl_xor_sync(0xffffffffu, s1, 1);
    s1 += __shfl_xor_sync(0xffffffffu, s1, 2);
    if ((lane & 3) == 0) {
        float bias0 = bo[0];
        int g0 = row0 + w * 16 + r_in;
        int g1 = g0 + 8;
        if (g0 < N_NODES) out[g0] = 1.f / (1.f + __expf(-(s0 + bias0)));
        if (g1 < N_NODES) out[g1] = 1.f / (1.f + __expf(-(s1 + bias0)));
    }
}

// -------------------------------- launcher ----------------------------------
extern "C" void kernel_launch(void* const* d_in, const int* in_sizes, int n_in,
                              void* d_out, int out_size) {
    const float* x    = (const float*)d_in[0];
    const int*   esrc = (const int*)  d_in[1];
    const int*   edst = (const int*)  d_in[2];
    const float* ew   = (const float*)d_in[3];
    const float* W1   = (const float*)d_in[4];
    const float* b1   = (const float*)d_in[5];
    const float* W2   = (const float*)d_in[6];
    const float* b2   = (const float*)d_in[7];
    const float* Wd   = (const float*)d_in[8];
    const float* bd   = (const float*)d_in[9];
    const float* Wo   = (const float*)d_in[10];
    const float* bo   = (const float*)d_in[11];
    float* out = (float*)d_out;

    __half* h1h;  __half* h2h;  float* h2f;
    cudaGetSymbolAddress((void**)&h1h,  g_h1h);
    cudaGetSymbolAddress((void**)&h2h,  g_h2h);
    cudaGetSymbolAddress((void**)&h2f,  g_h2f);

    static cudaStream_t s2 = nullptr;
    static cudaEvent_t evFork = nullptr, evJoin = nullptr;
    if (!s2) {
        cudaStreamCreateWithFlags(&s2, cudaStreamNonBlocking);
        cudaEventCreateWithFlags(&evFork, cudaEventDisableTiming);
        cudaEventCreateWithFlags(&evJoin, cudaEventDisableTiming);
    }

    const int aggBlocks   = (N_NODES * 32 + 255) / 256;
    const int gemmBlocks  = (N_NODES + 63) / 64;
    const int edge4Blocks = (N_EDGES / 4 + 255) / 256;   // 782 blocks

    // --- fork: gemm1 runs concurrent with the edge-bucket fill ---
    cudaEventRecord(evFork, 0);
    cudaStreamWaitEvent(s2, evFork, 0);
    gemm64_hmma_f32<<<gemmBlocks, 128, 0, s2>>>(x, W1, h1h);
    cudaEventRecord(evJoin, s2);

    // --- single-pass bucketed edge fill (g_cnt zero-at-entry invariant) ---
    fill_kernel<<<edge4Blocks, 256>>>(esrc, edst, ew);

    // --- join, then layer 1 aggregation ---
    cudaStreamWaitEvent(0, evJoin, 0);
    agg_swish_kernel<true, false><<<aggBlocks, 256>>>((const __half2*)h1h, b1, h2h);

    // --- layer 2 ---
    gemm64_hmma_f16<<<gemmBlocks, 128>>>(h2h, W2, h1h);
    agg_swish_kernel<false, true><<<aggBlocks, 256>>>((const __half2*)h1h, b2, h2f);

    // --- HMMA fused head ---
    head_hmma_kernel<<<gemmBlocks, 128>>>(h2f, Wd, bd, Wo, bo, out);
}

// round 16
// speedup vs baseline: 1.4487x; 1.4487x over previous
#include <cuda_runtime.h>
#include <cuda_fp16.h>

#define N_NODES 50000
#define N_EDGES 800000
#define SCAN_T  1024
#define CHUNK   49           // 1024*49 = 50176 >= 50000
#define SCAN_PAD (SCAN_T * CHUNK)

// -------- scratch (static device allocations; no cudaMalloc allowed) --------
__device__ __half g_h1h[N_NODES * 64];   // GEMM out (half) -> agg gather input
__device__ __half g_h2h[N_NODES * 64];   // agg1 out (half) -> gemm2 input
__device__ float  g_h2f[N_NODES * 64];   // agg2 out (fp32) -> head input
__device__ int    g_deg[N_NODES];
__device__ int    g_rowptr[N_NODES + 1];
__device__ int    g_rank[N_EDGES];       // edge rank within its dst bucket
__device__ int2   g_edge[N_EDGES];       // (src, weight-bits), dense CSR order

// ---------------------------- PTX helpers -----------------------------------
__device__ __forceinline__ unsigned smem_u32(const void* p) {
    return (unsigned)__cvta_generic_to_shared(p);
}
__device__ __forceinline__ void ldsm_x4(unsigned& r0, unsigned& r1,
                                        unsigned& r2, unsigned& r3, unsigned a) {
    asm volatile("ldmatrix.sync.aligned.m8n8.x4.shared.b16 {%0,%1,%2,%3},[%4];\n"
                 : "=r"(r0), "=r"(r1), "=r"(r2), "=r"(r3) : "r"(a));
}
__device__ __forceinline__ void ldsm_x4_t(unsigned& r0, unsigned& r1,
                                          unsigned& r2, unsigned& r3, unsigned a) {
    asm volatile("ldmatrix.sync.aligned.m8n8.x4.trans.shared.b16 {%0,%1,%2,%3},[%4];\n"
                 : "=r"(r0), "=r"(r1), "=r"(r2), "=r"(r3) : "r"(a));
}
__device__ __forceinline__ void mma16816(float* d, unsigned a0, unsigned a1,
                                         unsigned a2, unsigned a3,
                                         unsigned b0, unsigned b1) {
    asm volatile("mma.sync.aligned.m16n8k16.row.col.f32.f16.f16.f32 "
                 "{%0,%1,%2,%3},{%4,%5,%6,%7},{%8,%9},{%0,%1,%2,%3};\n"
                 : "+f"(d[0]), "+f"(d[1]), "+f"(d[2]), "+f"(d[3])
                 : "r"(a0), "r"(a1), "r"(a2), "r"(a3), "r"(b0), "r"(b1));
}

// ---------------------------- CSR construction -----------------------------
// hist also records each edge's rank within its destination bucket
__global__ void hist_kernel(const int* __restrict__ dst) {
    const int stride = gridDim.x * blockDim.x;
    int i = blockIdx.x * blockDim.x + threadIdx.x;
#pragma unroll
    for (int j = 0; j < 8; j++, i += stride) {
        if (i < N_EDGES) g_rank[i] = atomicAdd(&g_deg[dst[i]], 1);
    }
}

__global__ void scan_fused_kernel() {
    extern __shared__ int sdeg[];
    __shared__ int warpsum[32];
    int t = threadIdx.x;
    for (int i = t; i < SCAN_PAD; i += SCAN_T)
        sdeg[i] = (i < N_NODES) ? g_deg[i] : 0;
    __syncthreads();

    int base = t * CHUNK;
    int sum = 0;
    for (int j = 0; j < CHUNK; j++) sum += sdeg[base + j];

    int lane = t & 31, wid = t >> 5;
    int incl = sum;
#pragma unroll
    for (int o = 1; o < 32; o <<= 1) {
        int u = __shfl_up_sync(0xffffffffu, incl, o);
        if (lane >= o) incl += u;
    }
    if (lane == 31) warpsum[wid] = incl;
    __syncthreads();
    if (wid == 0) {
        int v = warpsum[lane];
        int wi = v;
#pragma unroll
        for (int o = 1; o < 32; o <<= 1) {
            int u = __shfl_up_sync(0xffffffffu, wi, o);
            if (lane >= o) wi += u;
        }
        warpsum[lane] = wi - v;
        if (lane == 31) g_rowptr[N_NODES] = wi;
    }
    __syncthreads();

    int run = warpsum[wid] + (incl - sum);
    for (int j = 0; j < CHUNK; j++) {
        int d = sdeg[base + j];
        sdeg[base + j] = run;
        run += d;
    }
    __syncthreads();
    for (int i = t; i < N_NODES; i += SCAN_T)
        g_rowptr[i] = sdeg[i];
}

// no atomics: pos = rowptr[dst] + rank
__global__ void scatter_kernel(const int* __restrict__ src,
                               const int* __restrict__ dst,
                               const float* __restrict__ w) {
    const int stride = gridDim.x * blockDim.x;
    int i = blockIdx.x * blockDim.x + threadIdx.x;
#pragma unroll
    for (int j = 0; j < 8; j++, i += stride) {
        if (i < N_EDGES) {
            int pos = g_rowptr[dst[i]] + g_rank[i];
            g_edge[pos] = make_int2(src[i], __float_as_int(w[i]));
        }
    }
}

// ------------------- HMMA GEMM: 64 rows x 64 cols per block -----------------
// fp32-input variant (layer 1: A = x)
__global__ void gemm64_hmma_f32(const float* __restrict__ A,
                                const float* __restrict__ W,
                                __half* __restrict__ outh) {
    __shared__ __align__(16) __half As[64 * 72];
    __shared__ __align__(16) __half Ws[64 * 72];
    const int tid  = threadIdx.x;
    const int lane = tid & 31;
    const int w    = tid >> 5;
    const int row0 = blockIdx.x * 64;

    const float4* W4 = reinterpret_cast<const float4*>(W);
    for (int i = tid; i < 1024; i += 128) {
        float4 v = W4[i];
        int k = i >> 4, n = (i & 15) * 4;
        __half2* p = reinterpret_cast<__half2*>(&Ws[k * 72 + n]);
        p[0] = __floats2half2_rn(v.x, v.y);
        p[1] = __floats2half2_rn(v.z, v.w);
    }
    const float4* A4 = reinterpret_cast<const float4*>(A);
    for (int i = tid; i < 1024; i += 128) {
        int r = i >> 4, k = (i & 15) * 4;
        int grow = row0 + r;
        float4 v = (grow < N_NODES) ? A4[grow * 16 + (k >> 2)]
                                    : make_float4(0.f, 0.f, 0.f, 0.f);
        __half2* p = reinterpret_cast<__half2*>(&As[r * 72 + k]);
        p[0] = __floats2half2_rn(v.x, v.y);
        p[1] = __floats2half2_rn(v.z, v.w);
    }
    __syncthreads();

    float d[4][2][4];
#pragma unroll
    for (int m = 0; m < 4; m++)
#pragma unroll
        for (int j = 0; j < 2; j++)
#pragma unroll
            for (int c = 0; c < 4; c++) d[m][j][c] = 0.f;

    const int lrow = lane & 15;
    const int lcol = (lane >> 4) * 8;

#pragma unroll
    for (int ks = 0; ks < 4; ks++) {
        const int kk = ks * 16;
        unsigned b0, b1, b2, b3;
        ldsm_x4_t(b0, b1, b2, b3,
                  smem_u32(&Ws[(kk + lrow) * 72 + w * 16 + lcol]));
#pragma unroll
        for (int m = 0; m < 4; m++) {
            unsigned a0, a1, a2, a3;
            ldsm_x4(a0, a1, a2, a3,
                    smem_u32(&As[(m * 16 + lrow) * 72 + kk + lcol]));
            mma16816(d[m][0], a0, a1, a2, a3, b0, b1);
            mma16816(d[m][1], a0, a1, a2, a3, b2, b3);
        }
    }

    __half2* out2 = reinterpret_cast<__half2*>(outh);
    const int r_in = lane >> 2;
    const int cpair = (lane & 3);
#pragma unroll
    for (int m = 0; m < 4; m++) {
#pragma unroll
        for (int j = 0; j < 2; j++) {
            int col2 = (w * 16 + j * 8) / 2 + cpair;
            int g0 = row0 + m * 16 + r_in;
            int g1 = g0 + 8;
            if (g0 < N_NODES)
                out2[g0 * 32 + col2] = __floats2half2_rn(d[m][j][0], d[m][j][1]);
            if (g1 < N_NODES)
                out2[g1 * 32 + col2] = __floats2half2_rn(d[m][j][2], d[m][j][3]);
        }
    }
}

// half-input variant (layer 2: A = agg1 half output)
__global__ void gemm64_hmma_f16(const __half* __restrict__ A,
                                const float* __restrict__ W,
                                __half* __restrict__ outh) {
    __shared__ __align__(16) __half As[64 * 72];
    __shared__ __align__(16) __half Ws[64 * 72];
    const int tid  = threadIdx.x;
    const int lane = tid & 31;
    const int w    = tid >> 5;
    const int row0 = blockIdx.x * 64;

    const float4* W4 = reinterpret_cast<const float4*>(W);
    for (int i = tid; i < 1024; i += 128) {
        float4 v = W4[i];
        int k = i >> 4, n = (i & 15) * 4;
        __half2* p = reinterpret_cast<__half2*>(&Ws[k * 72 + n]);
        p[0] = __floats2half2_rn(v.x, v.y);
        p[1] = __floats2half2_rn(v.z, v.w);
    }
    const uint2* A2 = reinterpret_cast<const uint2*>(A);
    for (int i = tid; i < 1024; i += 128) {
        int r = i >> 4, k4 = (i & 15);
        int grow = row0 + r;
        uint2 v = (grow < N_NODES) ? A2[grow * 16 + k4] : make_uint2(0u, 0u);
        *reinterpret_cast<uint2*>(&As[r * 72 + k4 * 4]) = v;
    }
    __syncthreads();

    float d[4][2][4];
#pragma unroll
    for (int m = 0; m < 4; m++)
#pragma unroll
        for (int j = 0; j < 2; j++)
#pragma unroll
            for (int c = 0; c < 4; c++) d[m][j][c] = 0.f;

    const int lrow = lane & 15;
    const int lcol = (lane >> 4) * 8;

#pragma unroll
    for (int ks = 0; ks < 4; ks++) {
        const int kk = ks * 16;
        unsigned b0, b1, b2, b3;
        ldsm_x4_t(b0, b1, b2, b3,
                  smem_u32(&Ws[(kk + lrow) * 72 + w * 16 + lcol]));
#pragma unroll
        for (int m = 0; m < 4; m++) {
            unsigned a0, a1, a2, a3;
            ldsm_x4(a0, a1, a2, a3,
                    smem_u32(&As[(m * 16 + lrow) * 72 + kk + lcol]));
            mma16816(d[m][0], a0, a1, a2, a3, b0, b1);
            mma16816(d[m][1], a0, a1, a2, a3, b2, b3);
        }
    }

    __half2* out2 = reinterpret_cast<__half2*>(outh);
    const int r_in = lane >> 2;
    const int cpair = (lane & 3);
#pragma unroll
    for (int m = 0; m < 4; m++) {
#pragma unroll
        for (int j = 0; j < 2; j++) {
            int col2 = (w * 16 + j * 8) / 2 + cpair;
            int g0 = row0 + m * 16 + r_in;
            int g1 = g0 + 8;
            if (g0 < N_NODES)
                out2[g0 * 32 + col2] = __floats2half2_rn(d[m][j][0], d[m][j][1]);
            if (g1 < N_NODES)
                out2[g1 * 32 + col2] = __floats2half2_rn(d[m][j][2], d[m][j][3]);
        }
    }
}

// -------------------- CSR aggregation + bias + swish ------------------------
// one warp per node; lane owns half2; 8x unroll for MLP (champion R8 form)
template<bool HALF_OUT>
__global__ void agg_swish_kernel(const __half2* __restrict__ hp,
                                 const float* __restrict__ bias,
                                 void* __restrict__ outv) {
    int node = (blockIdx.x * blockDim.x + threadIdx.x) >> 5;
    int lane = threadIdx.x & 31;
    if (node >= N_NODES) return;
    int beg = g_rowptr[node];
    int end = g_rowptr[node + 1];
    float2 acc = make_float2(0.f, 0.f);
    int e = beg;
    for (; e + 8 <= end; e += 8) {
        int2 ed[8];
#pragma unroll
        for (int j = 0; j < 8; j++) ed[j] = g_edge[e + j];
        float2 v[8];
#pragma unroll
        for (int j = 0; j < 8; j++) v[j] = __half22float2(hp[ed[j].x * 32 + lane]);
#pragma unroll
        for (int j = 0; j < 8; j++) {
            float w = __int_as_float(ed[j].y);
            acc.x = fmaf(w, v[j].x, acc.x);
            acc.y = fmaf(w, v[j].y, acc.y);
        }
    }
    for (; e + 2 <= end; e += 2) {
        int2 e0 = g_edge[e], e1 = g_edge[e + 1];
        float2 v0 = __half22float2(hp[e0.x * 32 + lane]);
        float2 v1 = __half22float2(hp[e1.x * 32 + lane]);
        float w0 = __int_as_float(e0.y), w1 = __int_as_float(e1.y);
        acc.x = fmaf(w0, v0.x, acc.x); acc.y = fmaf(w0, v0.y, acc.y);
        acc.x = fmaf(w1, v1.x, acc.x); acc.y = fmaf(w1, v1.y, acc.y);
    }
    if (e < end) {
        int2 e0 = g_edge[e];
        float2 v0 = __half22float2(hp[e0.x * 32 + lane]);
        float w0 = __int_as_float(e0.y);
        acc.x = fmaf(w0, v0.x, acc.x); acc.y = fmaf(w0, v0.y, acc.y);
    }
    float2 b = reinterpret_cast<const float2*>(bias)[lane];
    float ax = acc.x + b.x;
    float ay = acc.y + b.y;
    ax = ax / (1.f + __expf(-ax));
    ay = ay / (1.f + __expf(-ay));
    if (HALF_OUT) {
        reinterpret_cast<__half2*>(outv)[node * 32 + lane] = __floats2half2_rn(ax, ay);
    } else {
        reinterpret_cast<float2*>(outv)[node * 32 + lane] = make_float2(ax, ay);
    }
}

// -------- HMMA fused head: dense(100, swish) + dense(1, sigmoid) ------------
__global__ void head_hmma_kernel(const float* __restrict__ A,
                                 const float* __restrict__ Wd,
                                 const float* __restrict__ bd,
                                 const float* __restrict__ Wo,
                                 const float* __restrict__ bo,
                                 float* __restrict__ out) {
    __shared__ __align__(16) __half As[64 * 72];
    __shared__ __align__(16) __half Ws[64 * 120];   // [k][n], n padded to 112
    __shared__ float bdS[112];
    __shared__ float woS[112];
    const int tid  = threadIdx.x;
    const int lane = tid & 31;
    const int w    = tid >> 5;
    const int row0 = blockIdx.x * 64;

    for (int i = tid; i < 64 * 112; i += 128) {
        int k = i / 112, n = i % 112;
        float v = (n < 100) ? Wd[k * 100 + n] : 0.f;
        Ws[k * 120 + n] = __float2half_rn(v);
    }
    const float4* A4 = reinterpret_cast<const float4*>(A);
    for (int i = tid; i < 1024; i += 128) {
        int r = i >> 4, k = (i & 15) * 4;
        int grow = row0 + r;
        float4 v = (grow < N_NODES) ? A4[grow * 16 + (k >> 2)]
                                    : make_float4(0.f, 0.f, 0.f, 0.f);
        __half2* p = reinterpret_cast<__half2*>(&As[r * 72 + k]);
        p[0] = __floats2half2_rn(v.x, v.y);
        p[1] = __floats2half2_rn(v.z, v.w);
    }
    if (tid < 112) {
        bdS[tid] = (tid < 100) ? bd[tid] : 0.f;
        woS[tid] = (tid < 100) ? Wo[tid] : 0.f;
    }
    __syncthreads();

    float acc[14][4];
#pragma unroll
    for (int t = 0; t < 14; t++)
#pragma unroll
        for (int c = 0; c < 4; c++) acc[t][c] = 0.f;

    const int lrow = lane & 15;
    const int lcol = (lane >> 4) * 8;

#pragma unroll
    for (int ks = 0; ks < 4; ks++) {
        const int kk = ks * 16;
        unsigned a0, a1, a2, a3;
        ldsm_x4(a0, a1, a2, a3,
                smem_u32(&As[(w * 16 + lrow) * 72 + kk + lcol]));
#pragma unroll
        for (int t2 = 0; t2 < 7; t2++) {
            unsigned b0, b1, b2, b3;
            ldsm_x4_t(b0, b1, b2, b3,
                      smem_u32(&Ws[(kk + lrow) * 120 + t2 * 16 + lcol]));
            mma16816(acc[t2 * 2],     a0, a1, a2, a3, b0, b1);
            mma16816(acc[t2 * 2 + 1], a0, a1, a2, a3, b2, b3);
        }
    }

    const int r_in = lane >> 2;
    const int c2   = (lane & 3) * 2;
    float s0 = 0.f, s1 = 0.f;
#pragma unroll
    for (int t = 0; t < 14; t++) {
        int c = t * 8 + c2;
        float bb0 = bdS[c], bb1 = bdS[c + 1];
        float ww0 = woS[c], ww1 = woS[c + 1];
        float v;
        v = acc[t][0] + bb0; v = v / (1.f + __expf(-v)); s0 = fmaf(v, ww0, s0);
        v = acc[t][1] + bb1; v = v / (1.f + __expf(-v)); s0 = fmaf(v, ww1, s0);
        v = acc[t][2] + bb0; v = v / (1.f + __expf(-v)); s1 = fmaf(v, ww0, s1);
        v = acc[t][3] + bb1; v = v / (1.f + __expf(-v)); s1 = fmaf(v, ww1, s1);
    }
    s0 += __shfl_xor_sync(0xffffffffu, s0, 1);
    s0 += __shfl_xor_sync(0xffffffffu, s0, 2);
    s1 += __shfl_xor_sync(0xffffffffu, s1, 1);
    s1 += __shfl_xor_sync(0xffffffffu, s1, 2);
    if ((lane & 3) == 0) {
        float bias0 = bo[0];
        int g0 = row0 + w * 16 + r_in;
        int g1 = g0 + 8;
        if (g0 < N_NODES) out[g0] = 1.f / (1.f + __expf(-(s0 + bias0)));
        if (g1 < N_NODES) out[g1] = 1.f / (1.f + __expf(-(s1 + bias0)));
    }
}

// -------------------------------- launcher ----------------------------------
extern "C" void kernel_launch(void* const* d_in, const int* in_sizes, int n_in,
                              void* d_out, int out_size) {
    const float* x    = (const float*)d_in[0];
    const int*   esrc = (const int*)  d_in[1];
    const int*   edst = (const int*)  d_in[2];
    const float* ew   = (const float*)d_in[3];
    const float* W1   = (const float*)d_in[4];
    const float* b1   = (const float*)d_in[5];
    const float* W2   = (const float*)d_in[6];
    const float* b2   = (const float*)d_in[7];
    const float* Wd   = (const float*)d_in[8];
    const float* bd   = (const float*)d_in[9];
    const float* Wo   = (const float*)d_in[10];
    const float* bo   = (const float*)d_in[11];
    float* out = (float*)d_out;

    __half* h1h;  __half* h2h;  float* h2f;  int* degp;
    cudaGetSymbolAddress((void**)&h1h,  g_h1h);
    cudaGetSymbolAddress((void**)&h2h,  g_h2h);
    cudaGetSymbolAddress((void**)&h2f,  g_h2f);
    cudaGetSymbolAddress((void**)&degp, g_deg);

    static cudaStream_t s2 = nullptr;
    static cudaEvent_t evFork = nullptr, evJoin = nullptr;
    if (!s2) {
        cudaStreamCreateWithFlags(&s2, cudaStreamNonBlocking);
        cudaEventCreateWithFlags(&evFork, cudaEventDisableTiming);
        cudaEventCreateWithFlags(&evJoin, cudaEventDisableTiming);
        cudaFuncSetAttribute(scan_fused_kernel,
                             cudaFuncAttributeMaxDynamicSharedMemorySize,
                             SCAN_PAD * (int)sizeof(int));
    }

    const int aggBlocks   = (N_NODES * 32 + 255) / 256;
    const int gemmBlocks  = (N_NODES + 63) / 64;
    const int edge8Blocks = (N_EDGES / 8 + 255) / 256;

    // --- fork: gemm1 runs concurrent with the CSR build ---
    cudaEventRecord(evFork, 0);
    cudaStreamWaitEvent(s2, evFork, 0);
    gemm64_hmma_f32<<<gemmBlocks, 128, 0, s2>>>(x, W1, h1h);
    cudaEventRecord(evJoin, s2);

    // --- CSR build (main stream) ---
    cudaMemsetAsync(degp, 0, N_NODES * sizeof(int));
    hist_kernel<<<edge8Blocks, 256>>>(edst);
    scan_fused_kernel<<<1, SCAN_T, SCAN_PAD * sizeof(int)>>>();
    scatter_kernel<<<edge8Blocks, 256>>>(esrc, edst, ew);

    // --- join, then layer 1 aggregation ---
    cudaStreamWaitEvent(0, evJoin, 0);
    agg_swish_kernel<true><<<aggBlocks, 256>>>((const __half2*)h1h, b1, h2h);

    // --- layer 2 ---
    gemm64_hmma_f16<<<gemmBlocks, 128>>>(h2h, W2, h1h);
    agg_swish_kernel<false><<<aggBlocks, 256>>>((const __half2*)h1h, b2, h2f);

    // --- HMMA fused head ---
    head_hmma_kernel<<<gemmBlocks, 128>>>(h2f, Wd, bd, Wo, bo, out);
}